// round 4
// baseline (speedup 1.0000x reference)
#include <cuda_runtime.h>
#include <math.h>

#define NNB  16
#define NOB  8
#define SDIM 4
#define H1   64
#define ED   16
#define HP   64
#define XC   85      // 1 + 4 + 64 + 16
#define BMAX 131072

// SoA scratch: xT[f][b], stride BMAX
__device__ float g_xT[XC * BMAX];

// ---------------- transpose kernel: x[B][85] -> g_xT[85][BMAX] ----------------
__global__ void __launch_bounds__(256)
transpose_kernel(const float* __restrict__ x, int nb)
{
    __shared__ float tile[32][33];
    const int bBase = blockIdx.x * 32;
    const int fBase = blockIdx.y * 32;
    const int tx = threadIdx.x & 31;
    const int ty = threadIdx.x >> 5;    // 0..7

    #pragma unroll
    for (int r = ty; r < 32; r += 8) {
        const int b = bBase + r, f = fBase + tx;
        if (b < nb && f < XC)
            tile[r][tx] = x[(size_t)b * XC + f];
    }
    __syncthreads();
    #pragma unroll
    for (int r = ty; r < 32; r += 8) {
        const int f = fBase + r, b = bBase + tx;
        if (b < nb && f < XC)
            g_xT[(size_t)f * BMAX + b] = tile[tx][r];
    }
}

__device__ __forceinline__ void barrier_acc(float e0, float e1, float D,
                                            float& bx, float& by) {
    const float px = -e0, py = -e1;
    const float q  = fmaf(px, px, py * py);
    const float rq = rsqrtf(q);
    const float nrm = q * rq;                       // |P|
    const float s  = 0.05f * __fdividef(1.0f, nrm * (nrm - D));
    bx = fmaf(s, px, bx);
    by = fmaf(s, py, by);
}

__global__ void __launch_bounds__(256, 2)
bnet_kernel(const float* __restrict__ Wp1n, const float* __restrict__ bp1n,
            const float* __restrict__ Wp2n, const float* __restrict__ bp2n,
            const float* __restrict__ Wr1n, const float* __restrict__ br1n,
            const float* __restrict__ Wr2n, const float* __restrict__ br2n,
            const float* __restrict__ Wp1o, const float* __restrict__ bp1o,
            const float* __restrict__ Wp2o, const float* __restrict__ bp2o,
            const float* __restrict__ Wr1o, const float* __restrict__ br1o,
            const float* __restrict__ Wr2o, const float* __restrict__ br2o,
            const float* __restrict__ Wpsi1, const float* __restrict__ bpsi1,
            const float* __restrict__ Wpsi2, const float* __restrict__ bpsi2,
            float* __restrict__ out, int nb)
{
    __shared__ __align__(16) float sWp1n_t[H1 * 4];   // [h][4]
    __shared__ __align__(16) float sbp1n[H1];
    __shared__ __align__(16) float sWp2n[H1 * ED];
    __shared__ __align__(16) float sbp2n[ED];
    __shared__ __align__(16) float sWr1n[ED * H1];
    __shared__ __align__(16) float sbr1n[H1];
    __shared__ __align__(16) float sWr2n[H1 * ED];
    __shared__ __align__(16) float sbr2n[ED];
    __shared__ __align__(16) float sWp1o_t[H1 * 2];   // [h][2]
    __shared__ __align__(16) float sbp1o[H1];
    __shared__ __align__(16) float sWp2o[H1 * ED];
    __shared__ __align__(16) float sbp2o[ED];
    __shared__ __align__(16) float sWr1o[ED * H1];
    __shared__ __align__(16) float sbr1o[H1];
    __shared__ __align__(16) float sWr2o[H1 * ED];
    __shared__ __align__(16) float sbr2o[ED];
    __shared__ __align__(16) float sWpsi1[(2 * ED + SDIM) * HP];
    __shared__ __align__(16) float sbpsi1[HP];
    __shared__ __align__(16) float sWpsi2[HP * 2];
    __shared__ __align__(16) float sbpsi2[2];

    // ---- staging ----
    for (int i = threadIdx.x; i < H1 * 4; i += 256) {
        int h = i >> 2, k = i & 3;
        sWp1n_t[i] = Wp1n[k * H1 + h];
    }
    for (int i = threadIdx.x; i < H1 * 2; i += 256) {
        int h = i >> 1, k = i & 1;
        sWp1o_t[i] = Wp1o[k * H1 + h];
    }
    {
        float* dsts[18]       = { sbp1n, sWp2n, sbp2n, sWr1n, sbr1n, sWr2n, sbr2n,
                                  sbp1o, sWp2o, sbp2o, sWr1o, sbr1o, sWr2o, sbr2o,
                                  sWpsi1, sbpsi1, sWpsi2, sbpsi2 };
        const float* srcs[18] = { bp1n, Wp2n, bp2n, Wr1n, br1n, Wr2n, br2n,
                                  bp1o, Wp2o, bp2o, Wr1o, br1o, Wr2o, br2o,
                                  Wpsi1, bpsi1, Wpsi2, bpsi2 };
        const int ns[18]      = { H1, H1*ED, ED, ED*H1, H1, H1*ED, ED,
                                  H1, H1*ED, ED, ED*H1, H1, H1*ED, ED,
                                  (2*ED+SDIM)*HP, HP, HP*2, 2 };
        for (int a = 0; a < 18; ++a)
            for (int i = threadIdx.x; i < ns[a]; i += 256)
                dsts[a][i] = srcs[a][i];
    }
    __syncthreads();

    const int t = blockIdx.x * blockDim.x + threadIdx.x;
    if (t >= nb) return;

    // coalesced SoA access: feature f of element t
    #define XLD(f) g_xT[(size_t)(f) * BMAX + t]

    float bx = 0.f, by = 0.f;
    float rn[ED], ro[ED], sp[ED];

    // ======================= neighbor deep-set =======================
    {
        float hs[H1];
        #pragma unroll
        for (int h = 0; h < H1; ++h) hs[h] = 0.f;

        float c0 = XLD(5 + 0), c1 = XLD(5 + 1), c2 = XLD(5 + 2), c3 = XLD(5 + 3);

        #pragma unroll 1
        for (int j = 0; j < NNB; ++j) {
            float n0, n1, n2, n3;
            if (j < NNB - 1) {                      // prefetch next entity
                n0 = XLD(5 + 4 * j + 4);
                n1 = XLD(5 + 4 * j + 5);
                n2 = XLD(5 + 4 * j + 6);
                n3 = XLD(5 + 4 * j + 7);
            }
            barrier_acc(c0, c1, 0.3f, bx, by);
            #pragma unroll
            for (int h = 0; h < H1; ++h) {
                const float4 w = *reinterpret_cast<const float4*>(&sWp1n_t[h * 4]);
                float v = sbp1n[h];
                v = fmaf(c0, w.x, v);
                v = fmaf(c1, w.y, v);
                v = fmaf(c2, w.z, v);
                v = fmaf(c3, w.w, v);
                hs[h] += fmaxf(v, 0.f);
            }
            c0 = n0; c1 = n1; c2 = n2; c3 = n3;
        }

        #pragma unroll
        for (int o = 0; o < ED; ++o) sp[o] = (float)NNB * sbp2n[o];
        #pragma unroll
        for (int h = 0; h < H1; ++h) {
            const float v = hs[h];
            #pragma unroll
            for (int o = 0; o < ED; ++o) sp[o] = fmaf(v, sWp2n[h * ED + o], sp[o]);
        }
    }
    // rho_n (hidden chunked by 16)
    #pragma unroll
    for (int o = 0; o < ED; ++o) rn[o] = sbr2n[o];
    #pragma unroll 1
    for (int c = 0; c < 4; ++c) {
        const int base = c * 16;
        float hc[16];
        #pragma unroll
        for (int h = 0; h < 16; ++h) hc[h] = sbr1n[base + h];
        #pragma unroll
        for (int i = 0; i < ED; ++i) {
            const float v = sp[i];
            #pragma unroll
            for (int h = 0; h < 16; ++h)
                hc[h] = fmaf(v, sWr1n[i * H1 + base + h], hc[h]);
        }
        #pragma unroll
        for (int h = 0; h < 16; ++h) {
            const float v = fmaxf(hc[h], 0.f);
            #pragma unroll
            for (int o = 0; o < ED; ++o)
                rn[o] = fmaf(v, sWr2n[(base + h) * ED + o], rn[o]);
        }
    }

    // ======================= obstacle deep-set =======================
    {
        float hs[H1];
        #pragma unroll
        for (int h = 0; h < H1; ++h) hs[h] = 0.f;

        float c0 = XLD(69 + 0), c1 = XLD(69 + 1);

        #pragma unroll 1
        for (int j = 0; j < NOB; ++j) {
            float n0, n1;
            if (j < NOB - 1) {
                n0 = XLD(69 + 2 * j + 2);
                n1 = XLD(69 + 2 * j + 3);
            }
            barrier_acc(c0, c1, 0.3f, bx, by);
            #pragma unroll
            for (int h = 0; h < H1; ++h) {
                const float2 w = *reinterpret_cast<const float2*>(&sWp1o_t[h * 2]);
                float v = sbp1o[h];
                v = fmaf(c0, w.x, v);
                v = fmaf(c1, w.y, v);
                hs[h] += fmaxf(v, 0.f);
            }
            c0 = n0; c1 = n1;
        }

        #pragma unroll
        for (int o = 0; o < ED; ++o) sp[o] = (float)NOB * sbp2o[o];
        #pragma unroll
        for (int h = 0; h < H1; ++h) {
            const float v = hs[h];
            #pragma unroll
            for (int o = 0; o < ED; ++o) sp[o] = fmaf(v, sWp2o[h * ED + o], sp[o]);
        }
    }
    #pragma unroll
    for (int o = 0; o < ED; ++o) ro[o] = sbr2o[o];
    #pragma unroll 1
    for (int c = 0; c < 4; ++c) {
        const int base = c * 16;
        float hc[16];
        #pragma unroll
        for (int h = 0; h < 16; ++h) hc[h] = sbr1o[base + h];
        #pragma unroll
        for (int i = 0; i < ED; ++i) {
            const float v = sp[i];
            #pragma unroll
            for (int h = 0; h < 16; ++h)
                hc[h] = fmaf(v, sWr1o[i * H1 + base + h], hc[h]);
        }
        #pragma unroll
        for (int h = 0; h < 16; ++h) {
            const float v = fmaxf(hc[h], 0.f);
            #pragma unroll
            for (int o = 0; o < ED; ++o)
                ro[o] = fmaf(v, sWr2o[(base + h) * ED + o], ro[o]);
        }
    }

    // ======================= psi head (chunked) =======================
    const float g0 = XLD(1), g1 = XLD(2), g2 = XLD(3), g3 = XLD(4);
    float a0 = sbpsi2[0], a1 = sbpsi2[1];
    #pragma unroll 1
    for (int c = 0; c < 4; ++c) {
        const int base = c * 16;
        float hc[16];
        #pragma unroll
        for (int h = 0; h < 16; ++h) hc[h] = sbpsi1[base + h];
        #pragma unroll
        for (int i = 0; i < ED; ++i) {
            const float v = rn[i];
            #pragma unroll
            for (int h = 0; h < 16; ++h)
                hc[h] = fmaf(v, sWpsi1[i * HP + base + h], hc[h]);
        }
        #pragma unroll
        for (int i = 0; i < ED; ++i) {
            const float v = ro[i];
            #pragma unroll
            for (int h = 0; h < 16; ++h)
                hc[h] = fmaf(v, sWpsi1[(ED + i) * HP + base + h], hc[h]);
        }
        #pragma unroll
        for (int h = 0; h < 16; ++h) {
            float v = hc[h];
            v = fmaf(g0, sWpsi1[(2 * ED + 0) * HP + base + h], v);
            v = fmaf(g1, sWpsi1[(2 * ED + 1) * HP + base + h], v);
            v = fmaf(g2, sWpsi1[(2 * ED + 2) * HP + base + h], v);
            v = fmaf(g3, sWpsi1[(2 * ED + 3) * HP + base + h], v);
            v = fmaxf(v, 0.f);
            a0 = fmaf(v, sWpsi2[2 * (base + h) + 0], a0);
            a1 = fmaf(v, sWpsi2[2 * (base + h) + 1], a1);
        }
    }

    a0 = fmaf(2.0f, tanhf(a0), bx);
    a1 = fmaf(2.0f, tanhf(a1), by);

    const float inv = fmaxf(fmaxf(fabsf(a0), fabsf(a1)) * 0.5f, 1.0f);
    const float r   = __fdividef(1.0f, inv);
    float2 res;
    res.x = a0 * r;
    res.y = a1 * r;
    reinterpret_cast<float2*>(out)[t] = res;
    #undef XLD
}

extern "C" void kernel_launch(void* const* d_in, const int* in_sizes, int n_in,
                              void* d_out, int out_size) {
    const float* x     = (const float*)d_in[0];
    const float* Wp1n  = (const float*)d_in[1];
    const float* bp1n  = (const float*)d_in[2];
    const float* Wp2n  = (const float*)d_in[3];
    const float* bp2n  = (const float*)d_in[4];
    const float* Wr1n  = (const float*)d_in[5];
    const float* br1n  = (const float*)d_in[6];
    const float* Wr2n  = (const float*)d_in[7];
    const float* br2n  = (const float*)d_in[8];
    const float* Wp1o  = (const float*)d_in[9];
    const float* bp1o  = (const float*)d_in[10];
    const float* Wp2o  = (const float*)d_in[11];
    const float* bp2o  = (const float*)d_in[12];
    const float* Wr1o  = (const float*)d_in[13];
    const float* br1o  = (const float*)d_in[14];
    const float* Wr2o  = (const float*)d_in[15];
    const float* br2o  = (const float*)d_in[16];
    const float* Wpsi1 = (const float*)d_in[17];
    const float* bpsi1 = (const float*)d_in[18];
    const float* Wpsi2 = (const float*)d_in[19];
    const float* bpsi2 = (const float*)d_in[20];
    float* out = (float*)d_out;

    const int nb = in_sizes[0] / XC;

    dim3 tg((nb + 31) / 32, (XC + 31) / 32);
    transpose_kernel<<<tg, 256>>>(x, nb);

    const int threads = 256;
    const int blocks = (nb + threads - 1) / threads;
    bnet_kernel<<<blocks, threads>>>(
        Wp1n, bp1n, Wp2n, bp2n, Wr1n, br1n, Wr2n, br2n,
        Wp1o, bp1o, Wp2o, bp2o, Wr1o, br1o, Wr2o, br2o,
        Wpsi1, bpsi1, Wpsi2, bpsi2, out, nb);
}

// round 5
// speedup vs baseline: 2.0359x; 2.0359x over previous
#include <cuda_runtime.h>
#include <math.h>

#define NNB  16
#define NOB  8
#define SDIM 4
#define H1   64
#define ED   16
#define HP   64
#define XC   85      // 1 + 4 + 64 + 16
#define BMAX 131072

// SoA scratch: xT[f][b], stride BMAX
__device__ float g_xT[XC * BMAX];

// ---------------- transpose kernel: x[B][85] -> g_xT[85][BMAX] ----------------
__global__ void __launch_bounds__(256)
transpose_kernel(const float* __restrict__ x, int nb)
{
    __shared__ float tile[32][33];
    const int bBase = blockIdx.x * 32;
    const int fBase = blockIdx.y * 32;
    const int tx = threadIdx.x & 31;
    const int ty = threadIdx.x >> 5;

    #pragma unroll
    for (int r = ty; r < 32; r += 8) {
        const int b = bBase + r, f = fBase + tx;
        if (b < nb && f < XC)
            tile[r][tx] = x[(size_t)b * XC + f];
    }
    __syncthreads();
    #pragma unroll
    for (int r = ty; r < 32; r += 8) {
        const int f = fBase + r, b = bBase + tx;
        if (b < nb && f < XC)
            g_xT[(size_t)f * BMAX + b] = tile[tx][r];
    }
}

__device__ __forceinline__ void barrier_acc(float e0, float e1, float D,
                                            float& bx, float& by) {
    const float px = -e0, py = -e1;
    const float q  = fmaf(px, px, py * py);
    const float rq = rsqrtf(q);
    const float nrm = q * rq;
    const float s  = 0.05f * __fdividef(1.0f, nrm * (nrm - D));
    bx = fmaf(s, px, bx);
    by = fmaf(s, py, by);
}

__global__ void __launch_bounds__(256, 2)
bnet_kernel(const float* __restrict__ Wp1n, const float* __restrict__ bp1n,
            const float* __restrict__ Wp2n, const float* __restrict__ bp2n,
            const float* __restrict__ Wr1n, const float* __restrict__ br1n,
            const float* __restrict__ Wr2n, const float* __restrict__ br2n,
            const float* __restrict__ Wp1o, const float* __restrict__ bp1o,
            const float* __restrict__ Wp2o, const float* __restrict__ bp2o,
            const float* __restrict__ Wr1o, const float* __restrict__ br1o,
            const float* __restrict__ Wr2o, const float* __restrict__ br2o,
            const float* __restrict__ Wpsi1, const float* __restrict__ bpsi1,
            const float* __restrict__ Wpsi2, const float* __restrict__ bpsi2,
            float* __restrict__ out, int nb)
{
    __shared__ __align__(16) float sWp1n_t[H1 * 4];   // [h][4]
    __shared__ __align__(16) float sbp1n[H1];
    __shared__ __align__(16) float sWp2n[H1 * ED];
    __shared__ __align__(16) float sbp2n[ED];
    __shared__ __align__(16) float sWr1n[ED * H1];
    __shared__ __align__(16) float sbr1n[H1];
    __shared__ __align__(16) float sWr2n[H1 * ED];
    __shared__ __align__(16) float sbr2n[ED];
    __shared__ __align__(16) float sWp1o_t[H1 * 2];   // [h][2]
    __shared__ __align__(16) float sbp1o[H1];
    __shared__ __align__(16) float sWp2o[H1 * ED];
    __shared__ __align__(16) float sbp2o[ED];
    __shared__ __align__(16) float sWr1o[ED * H1];
    __shared__ __align__(16) float sbr1o[H1];
    __shared__ __align__(16) float sWr2o[H1 * ED];
    __shared__ __align__(16) float sbr2o[ED];
    __shared__ __align__(16) float sWpsi1[(2 * ED + SDIM) * HP];
    __shared__ __align__(16) float sbpsi1[HP];
    __shared__ __align__(16) float sWpsi2[HP * 2];
    __shared__ __align__(16) float sbpsi2[2];

    // ---- staging ----
    for (int i = threadIdx.x; i < H1 * 4; i += 256) {
        int h = i >> 2, k = i & 3;
        sWp1n_t[i] = Wp1n[k * H1 + h];
    }
    for (int i = threadIdx.x; i < H1 * 2; i += 256) {
        int h = i >> 1, k = i & 1;
        sWp1o_t[i] = Wp1o[k * H1 + h];
    }
    {
        float* dsts[18]       = { sbp1n, sWp2n, sbp2n, sWr1n, sbr1n, sWr2n, sbr2n,
                                  sbp1o, sWp2o, sbp2o, sWr1o, sbr1o, sWr2o, sbr2o,
                                  sWpsi1, sbpsi1, sWpsi2, sbpsi2 };
        const float* srcs[18] = { bp1n, Wp2n, bp2n, Wr1n, br1n, Wr2n, br2n,
                                  bp1o, Wp2o, bp2o, Wr1o, br1o, Wr2o, br2o,
                                  Wpsi1, bpsi1, Wpsi2, bpsi2 };
        const int ns[18]      = { H1, H1*ED, ED, ED*H1, H1, H1*ED, ED,
                                  H1, H1*ED, ED, ED*H1, H1, H1*ED, ED,
                                  (2*ED+SDIM)*HP, HP, HP*2, 2 };
        for (int a = 0; a < 18; ++a)
            for (int i = threadIdx.x; i < ns[a]; i += 256)
                dsts[a][i] = srcs[a][i];
    }
    __syncthreads();

    const int t = blockIdx.x * blockDim.x + threadIdx.x;
    if (t >= nb) return;

    float bx = 0.f, by = 0.f;
    float rn[ED], ro[ED], sp[ED];

    // ======================= neighbor deep-set =======================
    // 16 neighbors in 4 groups of 4; each weight LDS feeds 16 FMAs.
    {
        float hs[H1];
        #pragma unroll
        for (int h = 0; h < H1; ++h) hs[h] = 0.f;

        const float* xb = g_xT + 5 * BMAX + t;   // neighbor features 5..68
        float e[16], en[16];
        #pragma unroll
        for (int i = 0; i < 16; ++i) e[i] = xb[(size_t)i * BMAX];

        #pragma unroll 1
        for (int g = 0; g < 4; ++g) {
            if (g < 3) {
                const float* xn = xb + (size_t)(16 * (g + 1)) * BMAX;
                #pragma unroll
                for (int i = 0; i < 16; ++i) en[i] = xn[(size_t)i * BMAX];
            }
            #pragma unroll
            for (int k = 0; k < 4; ++k)
                barrier_acc(e[4 * k + 0], e[4 * k + 1], 0.3f, bx, by);

            #pragma unroll
            for (int h = 0; h < H1; ++h) {
                const float4 w = *reinterpret_cast<const float4*>(&sWp1n_t[h * 4]);
                const float b = sbp1n[h];
                float v0 = b, v1 = b, v2 = b, v3 = b;
                v0 = fmaf(e[0],  w.x, v0); v0 = fmaf(e[1],  w.y, v0);
                v0 = fmaf(e[2],  w.z, v0); v0 = fmaf(e[3],  w.w, v0);
                v1 = fmaf(e[4],  w.x, v1); v1 = fmaf(e[5],  w.y, v1);
                v1 = fmaf(e[6],  w.z, v1); v1 = fmaf(e[7],  w.w, v1);
                v2 = fmaf(e[8],  w.x, v2); v2 = fmaf(e[9],  w.y, v2);
                v2 = fmaf(e[10], w.z, v2); v2 = fmaf(e[11], w.w, v2);
                v3 = fmaf(e[12], w.x, v3); v3 = fmaf(e[13], w.y, v3);
                v3 = fmaf(e[14], w.z, v3); v3 = fmaf(e[15], w.w, v3);
                hs[h] += (fmaxf(v0, 0.f) + fmaxf(v1, 0.f))
                       + (fmaxf(v2, 0.f) + fmaxf(v3, 0.f));
            }
            #pragma unroll
            for (int i = 0; i < 16; ++i) e[i] = en[i];
        }

        #pragma unroll
        for (int o = 0; o < ED; ++o) sp[o] = (float)NNB * sbp2n[o];
        #pragma unroll
        for (int h = 0; h < H1; ++h) {
            const float v = hs[h];
            #pragma unroll
            for (int o = 0; o < ED; ++o) sp[o] = fmaf(v, sWp2n[h * ED + o], sp[o]);
        }
    }
    // rho_n (hidden chunked by 16)
    #pragma unroll
    for (int o = 0; o < ED; ++o) rn[o] = sbr2n[o];
    #pragma unroll 1
    for (int c = 0; c < 4; ++c) {
        const int base = c * 16;
        float hc[16];
        #pragma unroll
        for (int h = 0; h < 16; ++h) hc[h] = sbr1n[base + h];
        #pragma unroll
        for (int i = 0; i < ED; ++i) {
            const float v = sp[i];
            #pragma unroll
            for (int h = 0; h < 16; ++h)
                hc[h] = fmaf(v, sWr1n[i * H1 + base + h], hc[h]);
        }
        #pragma unroll
        for (int h = 0; h < 16; ++h) {
            const float v = fmaxf(hc[h], 0.f);
            #pragma unroll
            for (int o = 0; o < ED; ++o)
                rn[o] = fmaf(v, sWr2n[(base + h) * ED + o], rn[o]);
        }
    }

    // ======================= obstacle deep-set =======================
    // all 8 obstacles (16 floats) in regs, one h-pass.
    {
        float e[16];
        const float* xo = g_xT + 69 * BMAX + t;   // obstacle features 69..84
        #pragma unroll
        for (int i = 0; i < 16; ++i) e[i] = xo[(size_t)i * BMAX];

        #pragma unroll
        for (int k = 0; k < 8; ++k)
            barrier_acc(e[2 * k + 0], e[2 * k + 1], 0.3f, bx, by);

        float hs[H1];
        #pragma unroll
        for (int h = 0; h < H1; ++h) {
            const float2 w = *reinterpret_cast<const float2*>(&sWp1o_t[h * 2]);
            const float b = sbp1o[h];
            float acc0 = 0.f, acc1 = 0.f;
            #pragma unroll
            for (int k = 0; k < 8; k += 2) {
                float va = b, vb = b;
                va = fmaf(e[2 * k + 0], w.x, va);
                va = fmaf(e[2 * k + 1], w.y, va);
                vb = fmaf(e[2 * k + 2], w.x, vb);
                vb = fmaf(e[2 * k + 3], w.y, vb);
                acc0 += fmaxf(va, 0.f);
                acc1 += fmaxf(vb, 0.f);
            }
            hs[h] = acc0 + acc1;
        }

        #pragma unroll
        for (int o = 0; o < ED; ++o) sp[o] = (float)NOB * sbp2o[o];
        #pragma unroll
        for (int h = 0; h < H1; ++h) {
            const float v = hs[h];
            #pragma unroll
            for (int o = 0; o < ED; ++o) sp[o] = fmaf(v, sWp2o[h * ED + o], sp[o]);
        }
    }
    #pragma unroll
    for (int o = 0; o < ED; ++o) ro[o] = sbr2o[o];
    #pragma unroll 1
    for (int c = 0; c < 4; ++c) {
        const int base = c * 16;
        float hc[16];
        #pragma unroll
        for (int h = 0; h < 16; ++h) hc[h] = sbr1o[base + h];
        #pragma unroll
        for (int i = 0; i < ED; ++i) {
            const float v = sp[i];
            #pragma unroll
            for (int h = 0; h < 16; ++h)
                hc[h] = fmaf(v, sWr1o[i * H1 + base + h], hc[h]);
        }
        #pragma unroll
        for (int h = 0; h < 16; ++h) {
            const float v = fmaxf(hc[h], 0.f);
            #pragma unroll
            for (int o = 0; o < ED; ++o)
                ro[o] = fmaf(v, sWr2o[(base + h) * ED + o], ro[o]);
        }
    }

    // ======================= psi head (chunked) =======================
    const float g0 = g_xT[1 * BMAX + t], g1 = g_xT[2 * BMAX + t];
    const float g2 = g_xT[3 * BMAX + t], g3 = g_xT[4 * BMAX + t];
    float a0 = sbpsi2[0], a1 = sbpsi2[1];
    #pragma unroll 1
    for (int c = 0; c < 4; ++c) {
        const int base = c * 16;
        float hc[16];
        #pragma unroll
        for (int h = 0; h < 16; ++h) hc[h] = sbpsi1[base + h];
        #pragma unroll
        for (int i = 0; i < ED; ++i) {
            const float v = rn[i];
            #pragma unroll
            for (int h = 0; h < 16; ++h)
                hc[h] = fmaf(v, sWpsi1[i * HP + base + h], hc[h]);
        }
        #pragma unroll
        for (int i = 0; i < ED; ++i) {
            const float v = ro[i];
            #pragma unroll
            for (int h = 0; h < 16; ++h)
                hc[h] = fmaf(v, sWpsi1[(ED + i) * HP + base + h], hc[h]);
        }
        #pragma unroll
        for (int h = 0; h < 16; ++h) {
            float v = hc[h];
            v = fmaf(g0, sWpsi1[(2 * ED + 0) * HP + base + h], v);
            v = fmaf(g1, sWpsi1[(2 * ED + 1) * HP + base + h], v);
            v = fmaf(g2, sWpsi1[(2 * ED + 2) * HP + base + h], v);
            v = fmaf(g3, sWpsi1[(2 * ED + 3) * HP + base + h], v);
            v = fmaxf(v, 0.f);
            a0 = fmaf(v, sWpsi2[2 * (base + h) + 0], a0);
            a1 = fmaf(v, sWpsi2[2 * (base + h) + 1], a1);
        }
    }

    a0 = fmaf(2.0f, tanhf(a0), bx);
    a1 = fmaf(2.0f, tanhf(a1), by);

    const float inv = fmaxf(fmaxf(fabsf(a0), fabsf(a1)) * 0.5f, 1.0f);
    const float r   = __fdividef(1.0f, inv);
    float2 res;
    res.x = a0 * r;
    res.y = a1 * r;
    reinterpret_cast<float2*>(out)[t] = res;
}

extern "C" void kernel_launch(void* const* d_in, const int* in_sizes, int n_in,
                              void* d_out, int out_size) {
    const float* x     = (const float*)d_in[0];
    const float* Wp1n  = (const float*)d_in[1];
    const float* bp1n  = (const float*)d_in[2];
    const float* Wp2n  = (const float*)d_in[3];
    const float* bp2n  = (const float*)d_in[4];
    const float* Wr1n  = (const float*)d_in[5];
    const float* br1n  = (const float*)d_in[6];
    const float* Wr2n  = (const float*)d_in[7];
    const float* br2n  = (const float*)d_in[8];
    const float* Wp1o  = (const float*)d_in[9];
    const float* bp1o  = (const float*)d_in[10];
    const float* Wp2o  = (const float*)d_in[11];
    const float* bp2o  = (const float*)d_in[12];
    const float* Wr1o  = (const float*)d_in[13];
    const float* br1o  = (const float*)d_in[14];
    const float* Wr2o  = (const float*)d_in[15];
    const float* br2o  = (const float*)d_in[16];
    const float* Wpsi1 = (const float*)d_in[17];
    const float* bpsi1 = (const float*)d_in[18];
    const float* Wpsi2 = (const float*)d_in[19];
    const float* bpsi2 = (const float*)d_in[20];
    float* out = (float*)d_out;

    const int nb = in_sizes[0] / XC;

    dim3 tg((nb + 31) / 32, (XC + 31) / 32);
    transpose_kernel<<<tg, 256>>>(x, nb);

    const int threads = 256;
    const int blocks = (nb + threads - 1) / threads;
    bnet_kernel<<<blocks, threads>>>(
        Wp1n, bp1n, Wp2n, bp2n, Wr1n, br1n, Wr2n, br2n,
        Wp1o, bp1o, Wp2o, bp2o, Wr1o, br1o, Wr2o, br2o,
        Wpsi1, bpsi1, Wpsi2, bpsi2, out, nb);
}